// round 5
// baseline (speedup 1.0000x reference)
#include <cuda_runtime.h>

// ProbAttention (Informer ProbSparse) for B=2, L=4096, H=8, D=64, sample_k = n_top = 45.

#define Bb   2
#define Ll   4096
#define Hh   8
#define Dd   64
#define SSK  45          // sample_k == n_top
#define BH   (Bb*Hh)     // 16
#define NC   32          // kv chunks in phase 3
#define CK   128         // keys per chunk (NC*CK == Ll)
#define SST  132         // padded ss row stride (floats, mult of 4)
#define SST4 (SST/4)

typedef unsigned long long ull;

// ---- scratch (static device globals: no allocation allowed) ----
__device__ int    g_idx_is64;
__device__ int    g_idx32[Ll * SSK];
__device__ float  g_M[BH * Ll];
__device__ int    g_top[BH * SSK];
__device__ float  g_pmax[BH * NC * SSK];
__device__ float  g_psum[BH * NC * SSK];
__device__ float4 g_pout[BH * NC * SSK * (Dd / 4)];

// ---- f32x2 packed-FMA helpers ----
__device__ __forceinline__ ull fma2(ull a, ull b, ull c) {
    ull d;
    asm("fma.rn.f32x2 %0, %1, %2, %3;" : "=l"(d) : "l"(a), "l"(b), "l"(c));
    return d;
}
__device__ __forceinline__ ull pack2(float x, float y) {
    ull r;
    asm("mov.b64 %0, {%1, %2};" : "=l"(r) : "f"(x), "f"(y));
    return r;
}
__device__ __forceinline__ void unpack2(ull v, float& x, float& y) {
    asm("mov.b64 {%0, %1}, %2;" : "=f"(x), "=f"(y) : "l"(v));
}

// ---------------- K0a: detect index dtype (int32 vs int64) ----------------
__global__ void k0_detect(const unsigned* __restrict__ src) {
    __shared__ int nz;
    if (threadIdx.x == 0) nz = 0;
    __syncthreads();
    unsigned v = src[threadIdx.x * 2 + 1];
    if (v != 0u) atomicAdd(&nz, 1);
    __syncthreads();
    if (threadIdx.x == 0) g_idx_is64 = (nz == 0) ? 1 : 0;
}

// ---------------- K0b: normalize indices -> int32 ----------------
__global__ void k0_cvt(const void* __restrict__ src, int n) {
    int i = blockIdx.x * 256 + threadIdx.x;
    if (i < n) {
        if (g_idx_is64) g_idx32[i] = (int)((const long long*)src)[i];
        else            g_idx32[i] = ((const int*)src)[i];
    }
}

// ---------------- K1: sampled scores M (+ output zeroing prologue) ----------------
// One warp per (b,l). Coalesced: LDG t reads float4 index (32t + lane) -> 512B
// contiguous per LDG. Chunk 32t+lane belongs to head h = 2t + (lane>>4);
// reduce over the 16-lane half with 4 shfl_xor.
__global__ __launch_bounds__(256) void k1_score(const float4* __restrict__ q4,
                                                const float4* __restrict__ k4,
                                                float4* __restrict__ out4) {
    // zero the output: 1M float4 over 262144 threads -> 4 each
    {
        int t = blockIdx.x * 256 + threadIdx.x;
        float4 z = make_float4(0.f, 0.f, 0.f, 0.f);
        #pragma unroll
        for (int r = 0; r < 4; r++) out4[t + r * 262144] = z;
    }

    int w    = blockIdx.x * 8 + (threadIdx.x >> 5);
    int lane = threadIdx.x & 31;
    int b = w >> 12;
    int l = w & (Ll - 1);

    const float4* qp = q4 + (size_t)(b * Ll + l) * (Hh * Dd / 4);
    float4 qv[4];
    #pragma unroll
    for (int t = 0; t < 4; t++) qv[t] = qp[t * 32 + lane];

    float mx[4] = {-1e30f, -1e30f, -1e30f, -1e30f};
    float sm[4] = {0.f, 0.f, 0.f, 0.f};
    const int* ip = g_idx32 + l * SSK;

    #pragma unroll 2
    for (int s = 0; s < SSK; s++) {
        const float4* kp = k4 + (size_t)(b * Ll + ip[s]) * (Hh * Dd / 4);
        #pragma unroll
        for (int t = 0; t < 4; t++) {
            float4 kv = kp[t * 32 + lane];
            float p = qv[t].x*kv.x + qv[t].y*kv.y + qv[t].z*kv.z + qv[t].w*kv.w;
            p += __shfl_xor_sync(0xffffffffu, p, 8);
            p += __shfl_xor_sync(0xffffffffu, p, 4);
            p += __shfl_xor_sync(0xffffffffu, p, 2);
            p += __shfl_xor_sync(0xffffffffu, p, 1);
            mx[t] = fmaxf(mx[t], p);
            sm[t] += p;
        }
    }
    if ((lane & 15) == 0) {
        int half = lane >> 4;
        #pragma unroll
        for (int t = 0; t < 4; t++) {
            int h = 2 * t + half;
            g_M[(b * Hh + h) * Ll + l] = mx[t] - sm[t] * (1.0f / (float)Ll);
        }
    }
}

// ---------------- K2: top-45 per (b,h) ----------------
__device__ __forceinline__ ull packfi(float f, int idx) {
    unsigned u = __float_as_uint(f);
    u = (u & 0x80000000u) ? ~u : (u | 0x80000000u);   // order-preserving map
    return ((ull)u << 32) | (unsigned)idx;
}

// Phase 1: each warp extracts its sorted top-45 of its 512 elements.
// Phase 2: warp 0 merges the 8 sorted lists.
__global__ __launch_bounds__(256) void k2_topk() {
    int bh  = blockIdx.x;
    int tid = threadIdx.x;
    int wid = tid >> 5, lane = tid & 31;

    __shared__ ull lists[8][SSK];

    float v[16];
    int base = bh * Ll + wid * 512 + lane;
    #pragma unroll
    for (int i = 0; i < 16; i++) v[i] = g_M[base + 32 * i];

    unsigned used = 0;
    ull best = 0ull;
    #pragma unroll
    for (int i = 0; i < 16; i++) {
        ull pk = packfi(v[i], wid * 512 + lane + 32 * i);
        if (pk > best) best = pk;
    }

    for (int r = 0; r < SSK; r++) {
        ull pk = best;
        #pragma unroll
        for (int o = 16; o; o >>= 1) {
            ull t = __shfl_xor_sync(0xffffffffu, pk, o);
            if (t > pk) pk = t;
        }
        if (lane == 0) lists[wid][r] = pk;
        if (pk == best) {   // unique owner (idx embedded -> keys distinct)
            int i_rm = (int)(((unsigned)(pk & 0xffffffffu) - (unsigned)(wid * 512 + lane)) >> 5);
            used |= 1u << i_rm;
            best = 0ull;
            #pragma unroll
            for (int i = 0; i < 16; i++) {
                if (!((used >> i) & 1u)) {
                    ull p2 = packfi(v[i], wid * 512 + lane + 32 * i);
                    if (p2 > best) best = p2;
                }
            }
        }
    }
    __syncthreads();

    if (wid == 0) {
        ull cur = (lane < 8) ? lists[lane][0] : 0ull;
        int p = 1;
        for (int r = 0; r < SSK; r++) {
            ull m = cur;
            #pragma unroll
            for (int o = 4; o; o >>= 1) {
                ull t = __shfl_xor_sync(0xffffffffu, m, o);
                if (t > m) m = t;
            }
            if (lane < 8 && cur == m) {
                g_top[bh * SSK + r] = (int)(m & 0xffffffffu);
                cur = (p < SSK) ? lists[lane][p] : 0ull;
                p++;
            }
        }
    }
}

// ---------------- K3: split-KV sparse attention partials ----------------
// Grid (NC, BH), 256 threads. smem ~68KB -> 3 CTAs/SM.
// smem: qs2 (u-pair packed Q, 23x128 floats) | ks (128x64 swizzled, reused
// for V) | ss (45 x 132 padded) | tops
#define QS2F (23 * 128)
#define K3_SMEM ((QS2F + CK * Dd + SSK * SST) * 4 + 256)

// One S-phase pass over NI u-pairs starting at pair index I0; j in [0,CK).
template <int NI>
__device__ __forceinline__ void s_pass(int i0, int j, const float4* ks4,
                                       const ulonglong2* qsU, float* ss) {
    ull acc[NI];
    #pragma unroll
    for (int i = 0; i < NI; i++) acc[i] = 0ull;

    #pragma unroll 1
    for (int dc = 0; dc < 16; dc++) {
        float4 kr = ks4[j * 16 + (dc ^ (j & 7))];
        ull kk0 = pack2(kr.x, kr.x);
        ull kk1 = pack2(kr.y, kr.y);
        ull kk2 = pack2(kr.z, kr.z);
        ull kk3 = pack2(kr.w, kr.w);
        #pragma unroll
        for (int i = 0; i < NI; i++) {
            ulonglong2 qA = qsU[(i0 + i) * 32 + dc * 2];      // d = 4dc, 4dc+1
            ulonglong2 qB = qsU[(i0 + i) * 32 + dc * 2 + 1];  // d = 4dc+2, 4dc+3
            acc[i] = fma2(qA.x, kk0, acc[i]);
            acc[i] = fma2(qA.y, kk1, acc[i]);
            acc[i] = fma2(qB.x, kk2, acc[i]);
            acc[i] = fma2(qB.y, kk3, acc[i]);
        }
    }
    #pragma unroll
    for (int i = 0; i < NI; i++) {
        float lo, hi;
        unpack2(acc[i], lo, hi);
        int u = 2 * (i0 + i);
        ss[u * SST + j] = lo;
        if (u + 1 < SSK) ss[(u + 1) * SST + j] = hi;
    }
}

__global__ __launch_bounds__(256) void k3_attn(const float4* __restrict__ q4,
                                               const float4* __restrict__ k4g,
                                               const float4* __restrict__ v4g) {
    int c  = blockIdx.x;
    int bh = blockIdx.y;
    int b = bh >> 3, h = bh & 7;
    int tid = threadIdx.x;

    extern __shared__ float smem[];
    float* qs2f = smem;                   // 23*128 floats (u-pair packed Q)
    float* ks   = qs2f + QS2F;            // 128*64 floats
    float* ss   = ks + CK * Dd;           // 45*132 floats
    int*   tops = (int*)(ss + SSK * SST);
    float4*           ks4 = (float4*)ks;
    const ulonglong2* ksU = (const ulonglong2*)ks;
    const ulonglong2* qsU = (const ulonglong2*)qs2f;
    const float4*     ss4 = (const float4*)ss;

    if (tid < SSK) tops[tid] = g_top[bh * SSK + tid];
    __syncthreads();

    // stage Q in u-pair-packed layout: qs2f[(u>>1)*128 + 2d + (u&1)] = q[u][d]
    for (int i = tid; i < 46 * 16; i += 256) {
        int u = i >> 4, c4 = i & 15;
        float4 qv = (u < SSK)
            ? q4[((size_t)(b * Ll + tops[u]) * Hh + h) * (Dd / 4) + c4]
            : make_float4(0.f, 0.f, 0.f, 0.f);
        float* dst = qs2f + ((u >> 1) * 128 + 8 * c4) + (u & 1);
        dst[0] = qv.x; dst[2] = qv.y; dst[4] = qv.z; dst[6] = qv.w;
    }
    // stage K chunk, XOR-swizzled at float4 granularity
    int k0 = c * CK;
    for (int i = tid; i < CK * (Dd / 4); i += 256) {
        int row = i >> 4, c4 = i & 15;
        ks4[row * 16 + (c4 ^ (row & 7))] =
            k4g[((size_t)(b * Ll + k0 + row) * Hh + h) * (Dd / 4) + c4];
    }
    __syncthreads();

    // S-phase: j = tid&127; lower thread-half does u-pairs 0..11, upper 12..22
    {
        int j = tid & 127;
        if (tid < 128) s_pass<12>(0,  j, ks4, qsU, ss);
        else           s_pass<11>(12, j, ks4, qsU, ss);
    }
    __syncthreads();

    // partial softmax per row u (warp-per-row, 4 elems/lane)
    int wid = tid >> 5, lane = tid & 31;
    for (int u = wid; u < SSK; u += 8) {
        float x[4];
        float mxv = -1e30f;
        #pragma unroll
        for (int t = 0; t < 4; t++) { x[t] = ss[u * SST + lane + t * 32]; mxv = fmaxf(mxv, x[t]); }
        #pragma unroll
        for (int o = 16; o; o >>= 1) mxv = fmaxf(mxv, __shfl_xor_sync(0xffffffffu, mxv, o));
        float sum = 0.f;
        #pragma unroll
        for (int t = 0; t < 4; t++) { float p = __expf(0.125f * (x[t] - mxv)); x[t] = p; sum += p; }
        #pragma unroll
        for (int o = 16; o; o >>= 1) sum += __shfl_xor_sync(0xffffffffu, sum, o);
        #pragma unroll
        for (int t = 0; t < 4; t++) ss[u * SST + lane + t * 32] = x[t];
        if (lane == 0) {
            g_pmax[(bh * NC + c) * SSK + u] = 0.125f * mxv;
            g_psum[(bh * NC + c) * SSK + u] = sum;
        }
    }
    __syncthreads();

    // stage V chunk into the K buffer (same swizzle)
    for (int i = tid; i < CK * (Dd / 4); i += 256) {
        int row = i >> 4, c4 = i & 15;
        ks4[row * 16 + (c4 ^ (row & 7))] =
            v4g[((size_t)(b * Ll + k0 + row) * Hh + h) * (Dd / 4) + c4];
    }
    __syncthreads();

    // P@V: thread = (ug, d4); ug in [0,15) owns u = {3ug, 3ug+1, 3ug+2}
    int d4 = tid & 15, ug = tid >> 4;
    if (ug < 15) {
        int u0 = ug * 3;
        ull a0l = 0, a0h = 0, a1l = 0, a1h = 0, a2l = 0, a2h = 0;
        #pragma unroll 2
        for (int jq = 0; jq < CK / 4; jq++) {
            float4 P0 = ss4[u0 * SST4 + jq];            // broadcast (16 lanes)
            float4 P1 = ss4[(u0 + 1) * SST4 + jq];
            float4 P2 = ss4[(u0 + 2) * SST4 + jq];
            #pragma unroll
            for (int t = 0; t < 4; t++) {
                int jj = jq * 4 + t;
                ulonglong2 vv = ksU[jj * 16 + (d4 ^ (jj & 7))];
                float p0 = (t == 0) ? P0.x : (t == 1) ? P0.y : (t == 2) ? P0.z : P0.w;
                float p1 = (t == 0) ? P1.x : (t == 1) ? P1.y : (t == 2) ? P1.z : P1.w;
                float p2 = (t == 0) ? P2.x : (t == 1) ? P2.y : (t == 2) ? P2.z : P2.w;
                ull b0 = pack2(p0, p0), b1 = pack2(p1, p1), b2 = pack2(p2, p2);
                a0l = fma2(b0, vv.x, a0l);  a0h = fma2(b0, vv.y, a0h);
                a1l = fma2(b1, vv.x, a1l);  a1h = fma2(b1, vv.y, a1h);
                a2l = fma2(b2, vv.x, a2l);  a2h = fma2(b2, vv.y, a2h);
            }
        }
        ulonglong2* po = (ulonglong2*)g_pout;
        size_t baseo = ((size_t)(bh * NC + c) * SSK) * 16 + d4;
        po[baseo + (size_t)u0 * 16]       = make_ulonglong2(a0l, a0h);
        po[baseo + (size_t)(u0 + 1) * 16] = make_ulonglong2(a1l, a1h);
        po[baseo + (size_t)(u0 + 2) * 16] = make_ulonglong2(a2l, a2h);
    }
}

// ---------------- K4: combine partials + scatter ----------------
__global__ __launch_bounds__(256) void k4_combine(float4* __restrict__ out4) {
    int bh = blockIdx.x;
    int b = bh >> 3, h = bh & 7;
    for (int i = threadIdx.x; i < SSK * 16; i += 256) {
        int u = i >> 4, d4 = i & 15;
        float gm = -1e30f;
        #pragma unroll 8
        for (int cc = 0; cc < NC; cc++)
            gm = fmaxf(gm, g_pmax[(bh * NC + cc) * SSK + u]);
        float denom = 0.f;
        float4 a = make_float4(0.f, 0.f, 0.f, 0.f);
        #pragma unroll 8
        for (int cc = 0; cc < NC; cc++) {
            float w = __expf(g_pmax[(bh * NC + cc) * SSK + u] - gm);
            denom += g_psum[(bh * NC + cc) * SSK + u] * w;
            float4 po = g_pout[((bh * NC + cc) * SSK + u) * 16 + d4];
            a.x += w * po.x; a.y += w * po.y; a.z += w * po.z; a.w += w * po.w;
        }
        float inv = 1.0f / denom;
        a.x *= inv; a.y *= inv; a.z *= inv; a.w *= inv;
        int lsel = g_top[bh * SSK + u];
        out4[((size_t)(b * Ll + lsel) * Hh + h) * 16 + d4] = a;
    }
}

// ---------------- launch ----------------
extern "C" void kernel_launch(void* const* d_in, const int* in_sizes, int n_in,
                              void* d_out, int out_size) {
    const float4* q4 = (const float4*)d_in[0];
    const float4* k4 = (const float4*)d_in[1];
    const float4* v4 = (const float4*)d_in[2];
    const void* idxp = d_in[n_in - 1];
    for (int i = 0; i < n_in; i++)
        if (in_sizes[i] == Ll * SSK) idxp = d_in[i];
    float4* out4 = (float4*)d_out;

    cudaFuncSetAttribute(k3_attn, cudaFuncAttributeMaxDynamicSharedMemorySize, K3_SMEM);

    k0_detect<<<1, 128>>>((const unsigned*)idxp);
    k0_cvt<<<(Ll * SSK + 255) / 256, 256>>>(idxp, Ll * SSK);
    k1_score<<<Bb * Ll / 8, 256>>>(q4, k4, out4);
    k2_topk<<<BH, 256>>>();
    k3_attn<<<dim3(NC, BH), 256, K3_SMEM>>>(q4, k4, v4);
    k4_combine<<<BH, 256>>>(out4);
}

// round 7
// speedup vs baseline: 1.7159x; 1.7159x over previous
#include <cuda_runtime.h>

// ProbAttention (Informer ProbSparse) for B=2, L=4096, H=8, D=64, sample_k = n_top = 45.

#define Bb   2
#define Ll   4096
#define Hh   8
#define Dd   64
#define SSK  45          // sample_k == n_top
#define BH   (Bb*Hh)     // 16
#define NC   16          // kv chunks in phase 3
#define CK   256         // keys per chunk (NC*CK == Ll)
#define SST  257         // padded ss row stride (floats)

typedef unsigned long long ull;

// ---- scratch (static device globals: no allocation allowed) ----
__device__ int    g_idx_is64;
__device__ int    g_idx32[Ll * SSK];
__device__ float  g_M[BH * Ll];
__device__ int    g_top[BH * SSK];
__device__ float  g_pmax[BH * NC * SSK];
__device__ float  g_psum[BH * NC * SSK];
__device__ float4 g_pout[BH * NC * SSK * (Dd / 4)];

// ---- f32x2 packed-FMA helpers ----
__device__ __forceinline__ ull fma2(ull a, ull b, ull c) {
    ull d;
    asm("fma.rn.f32x2 %0, %1, %2, %3;" : "=l"(d) : "l"(a), "l"(b), "l"(c));
    return d;
}
__device__ __forceinline__ ull pack2(float x, float y) {
    ull r;
    asm("mov.b64 %0, {%1, %2};" : "=l"(r) : "f"(x), "f"(y));
    return r;
}
__device__ __forceinline__ void unpack2(ull v, float& x, float& y) {
    asm("mov.b64 {%0, %1}, %2;" : "=f"(x), "=f"(y) : "l"(v));
}

// ---------------- K0a: zero output ----------------
__global__ void k0_zero(float4* __restrict__ out4, int n4) {
    int i = blockIdx.x * 256 + threadIdx.x;
    if (i < n4) out4[i] = make_float4(0.f, 0.f, 0.f, 0.f);
}

// ---------------- K0b: detect index dtype (int32 vs int64) ----------------
__global__ void k0_detect(const unsigned* __restrict__ src) {
    __shared__ int nz;
    if (threadIdx.x == 0) nz = 0;
    __syncthreads();
    unsigned v = src[threadIdx.x * 2 + 1];
    if (v != 0u) atomicAdd(&nz, 1);
    __syncthreads();
    if (threadIdx.x == 0) g_idx_is64 = (nz == 0) ? 1 : 0;
}

// ---------------- K0c: normalize indices -> int32 ----------------
__global__ void k0_cvt(const void* __restrict__ src, int n) {
    int i = blockIdx.x * 256 + threadIdx.x;
    if (i < n) {
        if (g_idx_is64) g_idx32[i] = (int)((const long long*)src)[i];
        else            g_idx32[i] = ((const int*)src)[i];
    }
}

// ---------------- K1: sampled scores M ----------------
// One warp per (b,l). Coalesced: LDG t reads float4 index (32t + lane) -> 512B
// contiguous per LDG. Chunk 32t+lane belongs to head h = 2t + (lane>>4);
// reduce over the 16-lane half with 4 shfl_xor.
__global__ __launch_bounds__(256) void k1_score(const float4* __restrict__ q4,
                                                const float4* __restrict__ k4) {
    int w    = blockIdx.x * 8 + (threadIdx.x >> 5);
    int lane = threadIdx.x & 31;
    int b = w >> 12;
    int l = w & (Ll - 1);

    const float4* qp = q4 + (size_t)(b * Ll + l) * (Hh * Dd / 4);
    float4 qv[4];
    #pragma unroll
    for (int t = 0; t < 4; t++) qv[t] = qp[t * 32 + lane];

    float mx[4] = {-1e30f, -1e30f, -1e30f, -1e30f};
    float sm[4] = {0.f, 0.f, 0.f, 0.f};
    const int* ip = g_idx32 + l * SSK;

    #pragma unroll 2
    for (int s = 0; s < SSK; s++) {
        const float4* kp = k4 + (size_t)(b * Ll + ip[s]) * (Hh * Dd / 4);
        #pragma unroll
        for (int t = 0; t < 4; t++) {
            float4 kv = kp[t * 32 + lane];
            float p = qv[t].x*kv.x + qv[t].y*kv.y + qv[t].z*kv.z + qv[t].w*kv.w;
            p += __shfl_xor_sync(0xffffffffu, p, 8);
            p += __shfl_xor_sync(0xffffffffu, p, 4);
            p += __shfl_xor_sync(0xffffffffu, p, 2);
            p += __shfl_xor_sync(0xffffffffu, p, 1);
            mx[t] = fmaxf(mx[t], p);
            sm[t] += p;
        }
    }
    if ((lane & 15) == 0) {
        int half = lane >> 4;
        #pragma unroll
        for (int t = 0; t < 4; t++) {
            int h = 2 * t + half;
            g_M[(b * Hh + h) * Ll + l] = mx[t] - sm[t] * (1.0f / (float)Ll);
        }
    }
}

// ---------------- K2: top-45 per (b,h) via 4-round radix select ----------------
// Downstream only needs the SET of top-45 indices (order irrelevant), so:
// exact 45th-largest key via radix select on the order-preserving u32 map,
// then compact (strictly-greater, then equals to fill).
__global__ __launch_bounds__(256) void k2_topk() {
    int bh  = blockIdx.x;
    int tid = threadIdx.x;
    int wid = tid >> 5, lane = tid & 31;

    __shared__ unsigned hist[256];
    __shared__ unsigned warptot[8];
    __shared__ unsigned sh_pivot, sh_above;
    __shared__ int n_gt, n_eq;

    // load 16 values, map to order-preserving keys
    unsigned key[16];
    #pragma unroll
    for (int i = 0; i < 16; i++) {
        unsigned u = __float_as_uint(g_M[bh * Ll + i * 256 + tid]);
        key[i] = (u & 0x80000000u) ? ~u : (u | 0x80000000u);
    }

    unsigned prefix = 0, pmask = 0;
    int need = SSK;

    #pragma unroll
    for (int round = 0; round < 4; round++) {
        int shift = 24 - round * 8;
        hist[tid] = 0;
        if (tid == 0) { n_gt = 0; n_eq = 0; }
        __syncthreads();
        #pragma unroll
        for (int i = 0; i < 16; i++)
            if ((key[i] & pmask) == prefix)
                atomicAdd(&hist[(key[i] >> shift) & 255u], 1u);
        __syncthreads();

        // suffix sum over 256 bins: warp-local reverse scan + higher-warp totals
        unsigned x = hist[tid];
        unsigned s = x;
        #pragma unroll
        for (int o = 1; o < 32; o <<= 1) {
            unsigned y = __shfl_down_sync(0xffffffffu, s, o);
            if (lane + o < 32) s += y;
        }
        unsigned wt = __shfl_sync(0xffffffffu, s, 0);
        if (lane == 0) warptot[wid] = wt;
        __syncthreads();
        unsigned hs = 0;
        #pragma unroll
        for (int w2 = 0; w2 < 8; w2++)
            if (w2 > wid) hs += warptot[w2];
        unsigned S = s + hs;                    // count of candidates with digit >= tid
        unsigned above = S - x;                 // strictly greater digits
        if ((int)S >= need && (int)above < need) {  // unique pivot bin
            sh_pivot = (unsigned)tid;
            sh_above = above;
        }
        __syncthreads();
        prefix |= sh_pivot << shift;
        pmask  |= 0xffu << shift;
        need   -= (int)sh_above;
        __syncthreads();
    }

    // prefix == exact key of the 45th largest; need = #equals to take
    int base = bh * SSK;
    #pragma unroll
    for (int i = 0; i < 16; i++)
        if (key[i] > prefix) {
            int p = atomicAdd(&n_gt, 1);
            g_top[base + p] = i * 256 + tid;
        }
    __syncthreads();
    int gt = n_gt;     // == SSK - need
    #pragma unroll
    for (int i = 0; i < 16; i++)
        if (key[i] == prefix) {
            int e = atomicAdd(&n_eq, 1);
            if (e < need) g_top[base + gt + e] = i * 256 + tid;
        }
}

// ---------------- K3: split-KV sparse attention partials ----------------
// smem: qs2 (u-pair packed Q, 23x128 floats) | ks (256x64, swizzled, reused
// for V) | ss (45 x 257 padded) | tops
#define QS2F (23 * 128)
#define K3_SMEM ((QS2F + CK * Dd + SSK * SST) * 4 + 256)

// One S-phase pass over NI u-pairs starting at pair index I0.
template <int NI>
__device__ __forceinline__ void s_pass(int i0, int j, const float4* ks4,
                                       const ulonglong2* qsU, float* ss) {
    ull acc[NI];
    #pragma unroll
    for (int i = 0; i < NI; i++) acc[i] = 0ull;

    #pragma unroll 1
    for (int dc = 0; dc < 16; dc++) {
        float4 kr = ks4[j * 16 + (dc ^ (j & 7))];
        ull kk0 = pack2(kr.x, kr.x);
        ull kk1 = pack2(kr.y, kr.y);
        ull kk2 = pack2(kr.z, kr.z);
        ull kk3 = pack2(kr.w, kr.w);
        #pragma unroll
        for (int i = 0; i < NI; i++) {
            ulonglong2 qA = qsU[(i0 + i) * 32 + dc * 2];      // d = 4dc, 4dc+1
            ulonglong2 qB = qsU[(i0 + i) * 32 + dc * 2 + 1];  // d = 4dc+2, 4dc+3
            acc[i] = fma2(qA.x, kk0, acc[i]);
            acc[i] = fma2(qA.y, kk1, acc[i]);
            acc[i] = fma2(qB.x, kk2, acc[i]);
            acc[i] = fma2(qB.y, kk3, acc[i]);
        }
    }
    #pragma unroll
    for (int i = 0; i < NI; i++) {
        float lo, hi;
        unpack2(acc[i], lo, hi);
        int u = 2 * (i0 + i);
        ss[u * SST + j] = lo;
        if (u + 1 < SSK) ss[(u + 1) * SST + j] = hi;
    }
}

__global__ __launch_bounds__(256) void k3_attn(const float4* __restrict__ q4,
                                               const float4* __restrict__ k4g,
                                               const float4* __restrict__ v4g) {
    int c  = blockIdx.x;
    int bh = blockIdx.y;
    int b = bh >> 3, h = bh & 7;
    int tid = threadIdx.x;

    extern __shared__ float smem[];
    float* qs2f = smem;                   // 23*128 floats (u-pair packed Q)
    float* ks   = qs2f + QS2F;            // 16384 floats
    float* ss   = ks + CK * Dd;           // 45*257 floats
    int*   tops = (int*)(ss + SSK * SST);
    float4*           ks4 = (float4*)ks;
    const ulonglong2* ksU = (const ulonglong2*)ks;
    const ulonglong2* qsU = (const ulonglong2*)qs2f;

    if (tid < SSK) tops[tid] = g_top[bh * SSK + tid];
    __syncthreads();

    // stage Q in u-pair-packed layout: qs2f[(u>>1)*128 + 2d + (u&1)] = q[u][d]
    for (int i = tid; i < 46 * 16; i += 256) {
        int u = i >> 4, c4 = i & 15;
        float4 qv = (u < SSK)
            ? q4[((size_t)(b * Ll + tops[u]) * Hh + h) * (Dd / 4) + c4]
            : make_float4(0.f, 0.f, 0.f, 0.f);
        float* dst = qs2f + ((u >> 1) * 128 + 8 * c4) + (u & 1);
        dst[0] = qv.x; dst[2] = qv.y; dst[4] = qv.z; dst[6] = qv.w;
    }
    // stage K chunk, XOR-swizzled at float4 granularity
    int k0 = c * CK;
    for (int i = tid; i < CK * (Dd / 4); i += 256) {
        int row = i >> 4, c4 = i & 15;
        ks4[row * 16 + (c4 ^ (row & 7))] =
            k4g[((size_t)(b * Ll + k0 + row) * Hh + h) * (Dd / 4) + c4];
    }
    __syncthreads();

    // S-phase: thread j computes S[u][j] for all 45 u, two passes of u-pairs
    s_pass<12>(0,  tid, ks4, qsU, ss);
    s_pass<11>(12, tid, ks4, qsU, ss);
    __syncthreads();

    // partial softmax per row u (warp-per-row)
    int wid = tid >> 5, lane = tid & 31;
    for (int u = wid; u < SSK; u += 8) {
        float x[8];
        float mxv = -1e30f;
        #pragma unroll
        for (int t = 0; t < 8; t++) { x[t] = ss[u * SST + lane + t * 32]; mxv = fmaxf(mxv, x[t]); }
        #pragma unroll
        for (int o = 16; o; o >>= 1) mxv = fmaxf(mxv, __shfl_xor_sync(0xffffffffu, mxv, o));
        float sum = 0.f;
        #pragma unroll
        for (int t = 0; t < 8; t++) { float p = __expf(0.125f * (x[t] - mxv)); x[t] = p; sum += p; }
        #pragma unroll
        for (int o = 16; o; o >>= 1) sum += __shfl_xor_sync(0xffffffffu, sum, o);
        #pragma unroll
        for (int t = 0; t < 8; t++) ss[u * SST + lane + t * 32] = x[t];
        if (lane == 0) {
            g_pmax[(bh * NC + c) * SSK + u] = 0.125f * mxv;
            g_psum[(bh * NC + c) * SSK + u] = sum;
        }
    }
    __syncthreads();

    // stage V chunk into the K buffer (same swizzle)
    for (int i = tid; i < CK * (Dd / 4); i += 256) {
        int row = i >> 4, c4 = i & 15;
        ks4[row * 16 + (c4 ^ (row & 7))] =
            v4g[((size_t)(b * Ll + k0 + row) * Hh + h) * (Dd / 4) + c4];
    }
    __syncthreads();

    // P@V: thread = (ug, d4); ug in [0,15) owns u = {3ug, 3ug+1, 3ug+2}
    int d4 = tid & 15, ug = tid >> 4;
    if (ug < 15) {
        int u0 = ug * 3;
        ull a0l = 0, a0h = 0, a1l = 0, a1h = 0, a2l = 0, a2h = 0;
        #pragma unroll 4
        for (int jj = 0; jj < CK; jj++) {
            ulonglong2 vv = ksU[jj * 16 + (d4 ^ (jj & 7))];
            ull P0 = pack2(ss[u0 * SST + jj],       ss[u0 * SST + jj]);
            ull P1 = pack2(ss[(u0 + 1) * SST + jj], ss[(u0 + 1) * SST + jj]);
            ull P2 = pack2(ss[(u0 + 2) * SST + jj], ss[(u0 + 2) * SST + jj]);
            a0l = fma2(P0, vv.x, a0l);  a0h = fma2(P0, vv.y, a0h);
            a1l = fma2(P1, vv.x, a1l);  a1h = fma2(P1, vv.y, a1h);
            a2l = fma2(P2, vv.x, a2l);  a2h = fma2(P2, vv.y, a2h);
        }
        ulonglong2* po = (ulonglong2*)g_pout;
        size_t baseo = ((size_t)(bh * NC + c) * SSK) * 16 + d4;
        po[baseo + (size_t)u0 * 16]       = make_ulonglong2(a0l, a0h);
        po[baseo + (size_t)(u0 + 1) * 16] = make_ulonglong2(a1l, a1h);
        po[baseo + (size_t)(u0 + 2) * 16] = make_ulonglong2(a2l, a2h);
    }
}

// ---------------- K4: combine partials + scatter ----------------
__global__ __launch_bounds__(256) void k4_combine(float4* __restrict__ out4) {
    int bh = blockIdx.x;
    int b = bh >> 3, h = bh & 7;
    for (int i = threadIdx.x; i < SSK * 16; i += 256) {
        int u = i >> 4, d4 = i & 15;
        float gm = -1e30f;
        #pragma unroll
        for (int cc = 0; cc < NC; cc++)
            gm = fmaxf(gm, g_pmax[(bh * NC + cc) * SSK + u]);
        float denom = 0.f;
        float4 a = make_float4(0.f, 0.f, 0.f, 0.f);
        #pragma unroll
        for (int cc = 0; cc < NC; cc++) {
            float w = __expf(g_pmax[(bh * NC + cc) * SSK + u] - gm);
            denom += g_psum[(bh * NC + cc) * SSK + u] * w;
            float4 po = g_pout[((bh * NC + cc) * SSK + u) * 16 + d4];
            a.x += w * po.x; a.y += w * po.y; a.z += w * po.z; a.w += w * po.w;
        }
        float inv = 1.0f / denom;
        a.x *= inv; a.y *= inv; a.z *= inv; a.w *= inv;
        int lsel = g_top[bh * SSK + u];
        out4[((size_t)(b * Ll + lsel) * Hh + h) * 16 + d4] = a;
    }
}

// ---------------- launch ----------------
extern "C" void kernel_launch(void* const* d_in, const int* in_sizes, int n_in,
                              void* d_out, int out_size) {
    const float4* q4 = (const float4*)d_in[0];
    const float4* k4 = (const float4*)d_in[1];
    const float4* v4 = (const float4*)d_in[2];
    const void* idxp = d_in[n_in - 1];
    for (int i = 0; i < n_in; i++)
        if (in_sizes[i] == Ll * SSK) idxp = d_in[i];
    float4* out4 = (float4*)d_out;

    cudaFuncSetAttribute(k3_attn, cudaFuncAttributeMaxDynamicSharedMemorySize, K3_SMEM);

    int n4 = out_size / 4;
    k0_zero<<<(n4 + 255) / 256, 256>>>(out4, n4);
    k0_detect<<<1, 128>>>((const unsigned*)idxp);
    k0_cvt<<<(Ll * SSK + 255) / 256, 256>>>(idxp, Ll * SSK);
    k1_score<<<Bb * Ll / 8, 256>>>(q4, k4);
    k2_topk<<<BH, 256>>>();
    k3_attn<<<dim3(NC, BH), 256, K3_SMEM>>>(q4, k4, v4);
    k4_combine<<<BH, 256>>>(out4);
}